// round 2
// baseline (speedup 1.0000x reference)
#include <cuda_runtime.h>
#include <math.h>

// ---------------- problem constants ----------------
#define NPIX     32768        // 32 * 32 * 32 pixels
#define NE       1024         // codebook entries
#define KDIM     256          // embedding dim
#define BETA     0.25f
#define EPS_P    1e-10f

// output layout (concatenated, float32):
// [0]                loss
// [1 .. 8388608]     z_q      (B,C,H,W) = same linear layout as input z
// [8388609]          perplexity
// [8388610 ..]       idx (32768, cast to float)
// [8421378 ..]       z_q1     (same layout as z)
#define ZQ_OFF    1ull
#define PERP_OFF  8388609ull
#define IDX_OFF   8388610ull
#define ZQ1_OFF   8421378ull

// ---------------- argmin GEMM tiling ----------------
#define MT   128              // pixels per CTA
#define CT   128              // codes per tile
#define KT   32               // k per B-tile
// Bs layout: float2 pairs, pair-major: pair p holds codes (2p, 2p+1) for k=0..31,
// padded stride 33 float2 (66 floats) per pair -> conflict-free 64-bit reads.
#define BS_PAIR_STRIDE 33     // in float2 units (32 k-values + 1 pad)
#define SMEM_A_FLOATS  (KDIM * MT)                 // 32768
#define SMEM_B_FLOATS  (64 * BS_PAIR_STRIDE * 2)   // 4224
#define SMEM_H_FLOATS  (NE)                        // 1024
#define SMEM_ARGMIN_BYTES ((SMEM_A_FLOATS + SMEM_B_FLOATS + SMEM_H_FLOATS) * 4)

// ---------------- device scratch ----------------
__device__ int   g_idx[NPIX];
__device__ float g_hn[NE];
__device__ float g_partials[1024];
__device__ int   g_hist[NE];

// ---------------- f32x2 helpers ----------------
__device__ __forceinline__ unsigned long long pack2(float lo, float hi) {
    unsigned long long r;
    asm("mov.b64 %0, {%1, %2};" : "=l"(r) : "f"(lo), "f"(hi));
    return r;
}
__device__ __forceinline__ void unpack2(unsigned long long v, float& lo, float& hi) {
    asm("mov.b64 {%0, %1}, %2;" : "=f"(lo), "=f"(hi) : "l"(v));
}
__device__ __forceinline__ void fma2(unsigned long long& d, unsigned long long a, unsigned long long b) {
    asm("fma.rn.f32x2 %0, %1, %2, %0;" : "+l"(d) : "l"(a), "l"(b));
}

// ---------------- kernel 0: half squared norms of codebook ----------------
__global__ void halfnorm_kernel(const float* __restrict__ emb) {
    int c = blockIdx.x * 256 + threadIdx.x;   // 0..1023
    const float* e = emb + c * KDIM;
    float s = 0.0f;
    #pragma unroll
    for (int i = 0; i < KDIM; i += 4) {
        float4 v = *(const float4*)(e + i);
        s += v.x * v.x + v.y * v.y + v.z * v.z + v.w * v.w;
    }
    g_hn[c] = 0.5f * s;
}

// ---------------- kernel A: argmax(z.e - 0.5||e||^2) over 1024 codes ----------------
// grid 256 blocks x 256 threads. thread (tx=t&15, ty=t>>4) computes
// pixels {8*ty + i, i<8} x codes {32*j + 2*tx + s, j<4, s<2} per code tile.
__global__ void __launch_bounds__(256, 1)
argmin_kernel(const float* __restrict__ z, const float* __restrict__ emb) {
    extern __shared__ float sm[];
    float* As = sm;                                   // [k][m] : KDIM x MT
    float* Bsf = sm + SMEM_A_FLOATS;                  // pair-major float2 tiles
    float* hn = sm + SMEM_A_FLOATS + SMEM_B_FLOATS;   // [1024]
    unsigned long long* Bs64 = (unsigned long long*)Bsf;

    const int t  = threadIdx.x;
    const int tx = t & 15;
    const int ty = t >> 4;
    const int m0 = blockIdx.x * MT;
    const float* zb = z + (size_t)(m0 >> 10) * (KDIM * 1024) + (m0 & 1023);

    // load A tile: As[k*128 + m], full K, coalesced float4
    #pragma unroll
    for (int r = 0; r < 32; r++) {
        int q = t + 256 * r;                // 0..8191 float4s
        int k = q >> 5;
        int m4 = (q & 31) << 2;
        float4 v = *(const float4*)(zb + (size_t)k * 1024 + m4);
        *(float4*)(As + k * MT + m4) = v;
    }
    // load half-norms
    #pragma unroll
    for (int r = 0; r < 4; r++) hn[t + 256 * r] = g_hn[t + 256 * r];

    float best[8];
    int   bidx[8];
    #pragma unroll
    for (int i = 0; i < 8; i++) { best[i] = -INFINITY; bidx[i] = 0; }

    for (int ct = 0; ct < NE / CT; ct++) {
        unsigned long long acc[8][4];
        #pragma unroll
        for (int i = 0; i < 8; i++)
            #pragma unroll
            for (int j = 0; j < 4; j++) acc[i][j] = 0ull;

        for (int kt = 0; kt < KDIM / KT; kt++) {
            __syncthreads();
            // load B tile: 128 codes x 32 k, store as float2 pairs [pair][k]
            #pragma unroll
            for (int r = 0; r < 4; r++) {
                int q = t + 256 * r;            // 0..1023 float4s
                int code = q >> 3;              // 0..127
                int kv = (q & 7) << 2;          // 0..28
                float4 v = *(const float4*)(emb + (size_t)(ct * CT + code) * KDIM + kt * KT + kv);
                int base = (code >> 1) * (BS_PAIR_STRIDE * 2) + (code & 1);
                Bsf[base + (kv + 0) * 2] = v.x;
                Bsf[base + (kv + 1) * 2] = v.y;
                Bsf[base + (kv + 2) * 2] = v.z;
                Bsf[base + (kv + 3) * 2] = v.w;
            }
            __syncthreads();

            #pragma unroll 8
            for (int kk = 0; kk < KT; kk++) {
                int k = kt * KT + kk;
                float4 a0 = *(const float4*)(As + k * MT + ty * 8);
                float4 a1 = *(const float4*)(As + k * MT + ty * 8 + 4);
                unsigned long long a2[8];
                a2[0] = pack2(a0.x, a0.x); a2[1] = pack2(a0.y, a0.y);
                a2[2] = pack2(a0.z, a0.z); a2[3] = pack2(a0.w, a0.w);
                a2[4] = pack2(a1.x, a1.x); a2[5] = pack2(a1.y, a1.y);
                a2[6] = pack2(a1.z, a1.z); a2[7] = pack2(a1.w, a1.w);
                unsigned long long b2[4];
                #pragma unroll
                for (int j = 0; j < 4; j++)
                    b2[j] = Bs64[(j * 16 + tx) * BS_PAIR_STRIDE + kk];
                #pragma unroll
                for (int i = 0; i < 8; i++)
                    #pragma unroll
                    for (int j = 0; j < 4; j++)
                        fma2(acc[i][j], a2[i], b2[j]);
            }
        }

        // epilogue for this code tile
        #pragma unroll
        for (int i = 0; i < 8; i++) {
            #pragma unroll
            for (int j = 0; j < 4; j++) {
                float lo, hi;
                unpack2(acc[i][j], lo, hi);
                int c0 = ct * CT + j * 32 + 2 * tx;
                float vlo = lo - hn[c0];
                float vhi = hi - hn[c0 + 1];
                if (vlo > best[i]) { best[i] = vlo; bidx[i] = c0; }
                if (vhi > best[i]) { best[i] = vhi; bidx[i] = c0 + 1; }
            }
        }
    }

    // reduce across the 16 tx lanes sharing each pixel row (tie -> lower idx)
    #pragma unroll
    for (int i = 0; i < 8; i++) {
        float v = best[i];
        int id = bidx[i];
        #pragma unroll
        for (int m = 8; m >= 1; m >>= 1) {
            float ov = __shfl_xor_sync(0xffffffffu, v, m);
            int   oi = __shfl_xor_sync(0xffffffffu, id, m);
            if (ov > v || (ov == v && oi < id)) { v = ov; id = oi; }
        }
        if (tx == 0) g_idx[m0 + ty * 8 + i] = id;
    }
}

// ---------------- kernel B1: gather z_q/z_q1 + squared-error partials ----------------
// block handles 32 consecutive pixels (within one b), 256 threads
__global__ void __launch_bounds__(256)
gather_kernel(const float* __restrict__ z, const float* __restrict__ emb,
              float* __restrict__ out) {
    __shared__ float se[32][257];
    __shared__ int sidx[32];
    __shared__ float red[256];
    const int t = threadIdx.x;
    const int n0 = blockIdx.x * 32;
    if (t < 32) sidx[t] = g_idx[n0 + t];
    __syncthreads();
    // load 32 codebook rows into smem (coalesced)
    #pragma unroll
    for (int r = 0; r < 8; r++) {
        int q = t + 256 * r;            // 0..2047 float4s
        int row = q >> 6;
        int c4 = (q & 63) << 2;
        float4 v = *(const float4*)(emb + (size_t)sidx[row] * KDIM + c4);
        se[row][c4 + 0] = v.x; se[row][c4 + 1] = v.y;
        se[row][c4 + 2] = v.z; se[row][c4 + 3] = v.w;
    }
    __syncthreads();
    const int hw = t & 31;
    const int cg = t >> 5;
    const int b = n0 >> 10;
    const int hwg = (n0 & 1023) + hw;
    const size_t zbase = (size_t)b * (KDIM * 1024) + hwg;
    float acc = 0.0f;
    #pragma unroll
    for (int ci = 0; ci < 32; ci++) {
        int c = cg * 32 + ci;
        float v = se[hw][c];
        size_t off = zbase + (size_t)c * 1024;
        float zv = z[off];
        float d = v - zv;
        acc += d * d;
        out[ZQ_OFF + off] = v;
        out[ZQ1_OFF + off] = v;
    }
    red[t] = acc;
    __syncthreads();
    #pragma unroll
    for (int s = 128; s > 0; s >>= 1) {
        if (t < s) red[t] += red[t + s];
        __syncthreads();
    }
    if (t == 0) g_partials[blockIdx.x] = red[0];
}

// ---------------- kernel B2: histogram + idx-as-float output ----------------
__global__ void hist_kernel(float* __restrict__ out) {
    __shared__ int h[NE];
    const int t = threadIdx.x;   // 1024 threads, 1 block
    h[t] = 0;
    __syncthreads();
    for (int n = t; n < NPIX; n += 1024) {
        int id = g_idx[n];
        atomicAdd(&h[id], 1);
        out[IDX_OFF + n] = (float)id;
    }
    __syncthreads();
    g_hist[t] = h[t];
}

// ---------------- kernel B3: loss + perplexity ----------------
__global__ void finalize_kernel(float* __restrict__ out) {
    __shared__ float red[1024];
    const int t = threadIdx.x;   // 1024 threads, 1 block
    red[t] = g_partials[t];
    __syncthreads();
    #pragma unroll
    for (int s = 512; s > 0; s >>= 1) {
        if (t < s) red[t] += red[t + s];
        __syncthreads();
    }
    float loss = red[0] * (1.0f + BETA) / 8388608.0f;
    __syncthreads();
    float p = (float)g_hist[t] / (float)NPIX;
    red[t] = p * logf(p + EPS_P);
    __syncthreads();
    #pragma unroll
    for (int s = 512; s > 0; s >>= 1) {
        if (t < s) red[t] += red[t + s];
        __syncthreads();
    }
    if (t == 0) {
        out[0] = loss;
        out[PERP_OFF] = expf(-red[0]);
    }
}

// ---------------- launch ----------------
extern "C" void kernel_launch(void* const* d_in, const int* in_sizes, int n_in,
                              void* d_out, int out_size) {
    const float* z   = (const float*)d_in[0];
    const float* emb = (const float*)d_in[1];
    float* out = (float*)d_out;

    halfnorm_kernel<<<4, 256>>>(emb);

    cudaFuncSetAttribute(argmin_kernel,
                         cudaFuncAttributeMaxDynamicSharedMemorySize,
                         SMEM_ARGMIN_BYTES);
    argmin_kernel<<<NPIX / MT, 256, SMEM_ARGMIN_BYTES>>>(z, emb);

    gather_kernel<<<NPIX / 32, 256>>>(z, emb, out);
    hist_kernel<<<1, 1024>>>(out);
    finalize_kernel<<<1, 1024>>>(out);
}